// round 4
// baseline (speedup 1.0000x reference)
#include <cuda_runtime.h>
#include <cuda_bf16.h>
#include <cstdint>

// MaddnessConv2d, round 4: 8 lanes/pixel, structurally conflict-free LDS,
// high occupancy (32 warps/SM), shuffle-assembled codes, smem-transposed stores.
//
//   x:            (16, 64, 56, 56) f32
//   split_idxs:   (16, 4) i32
//   split_vals:   (16, 4, 8) f32
//   lookup_tables:(16, 16, 64) f32
//   bias:         (64,) f32
//   out:          (16, 64, 56, 56) f32
//
// Per pixel: 16 4-bit codes (4 threshold steps on 4 fixed gathered x scalars
// per codebook), then out[ch] = sum_cb LUT[cb][e_cb][ch] + bias[ch].
//
// 8 lanes share a pixel (part = lane&7). Each LDS.128 phase (8 lanes) is ONE
// pixel reading ONE LUT row at slots {part} then {part+8}: 8 distinct banks,
// conflict-free independent of the code e. Lane accumulates channel groups
// {part, part+8} -> 8 accumulator registers.

#define NCB   16
#define KENC  16
#define HW    3136          // 56*56
#define WID   56
#define NPIX  50176         // 16*56*56
#define TPB   512
#define NBLK  784           // 784*512 == 8*50176 exactly; 64 pixels/block

// dynamic smem layout:
//   float4 s_lut[16*16*16]   65536 B  (identity layout; reused as transpose buf)
//   float  s_bias[64]          256 B
//   float  s_sval[16*4*8]     2048 B
//   int    s_off[64]           256 B
//   int    s_kpos[64]          256 B
#define SMEM_BYTES (65536 + 256 + 2048 + 256 + 256)

#define ADD_F32X2(out, a, b) \
    asm("add.rn.f32x2 %0, %1, %2;" : "=l"(out) : "l"(a), "l"(b))
#define PACK_F32X2(out, lo, hi) \
    asm("mov.b64 %0, {%1, %2};" : "=l"(out) : "f"(lo), "f"(hi))
#define UNPACK_F32X2(lo, hi, in) \
    asm("mov.b64 {%0, %1}, %2;" : "=f"(lo), "=f"(hi) : "l"(in))

__global__ __launch_bounds__(TPB, 2) void maddness_conv2d_kernel(
    const float* __restrict__ x,
    const int*   __restrict__ split_idxs,
    const float* __restrict__ split_vals,
    const float* __restrict__ lut,
    const float* __restrict__ bias,
    float*       __restrict__ out)
{
    extern __shared__ char smem_raw[];
    float4* s_lut  = (float4*)smem_raw;
    float*  s_bias = (float*)(smem_raw + 65536);
    float*  s_sval = (float*)(smem_raw + 65536 + 256);
    int*    s_off  = (int*)  (smem_raw + 65536 + 256 + 2048);
    int*    s_kpos = (int*)  (smem_raw + 65536 + 256 + 2048 + 256);

    const int tid = threadIdx.x;

    // --- cooperative smem fill (LUT identity layout) ---
    const float4* lut4 = (const float4*)lut;
    #pragma unroll
    for (int i = tid; i < NCB * KENC * 16; i += TPB) s_lut[i] = lut4[i];
    if (tid < 64) {
        int cb = tid >> 2;                     // tid = cb*4 + t
        int si = split_idxs[tid];
        int f  = cb * 36 + si;
        int ch = f / 9;
        int r  = f - ch * 9;                   // kernel position 0..8
        int dy = r / 3 - 1;
        int dx = r - (r / 3) * 3 - 1;
        s_off[tid]  = ch * HW + dy * WID + dx;
        s_kpos[tid] = r;
        s_bias[tid] = bias[tid];
    }
    if (tid < NCB * 32) s_sval[tid] = split_vals[tid];
    __syncthreads();

    // --- indices: 8 lanes per pixel ---
    const int gt   = blockIdx.x * TPB + tid;   // exact grid
    const int p    = gt >> 3;                  // pixel
    const int part = gt & 7;                   // lane role within pixel
    const int b    = p / HW;
    const int rem  = p - b * HW;
    const int y    = rem / WID;
    const int xw   = rem - y * WID;
    const float* xb = x + (size_t)b * 64 * HW + rem;

    // 3x3 validity bitmask (pad=1)
    unsigned vm = 0;
    #pragma unroll
    for (int ki = 0; ki < 3; ki++)
        #pragma unroll
        for (int kj = 0; kj < 3; kj++) {
            bool ok = ((unsigned)(y + ki - 1) < 56u) & ((unsigned)(xw + kj - 1) < 56u);
            vm |= (ok ? 1u : 0u) << (ki * 3 + kj);
        }

    // --- encode my 2 codebooks (cb = 2*part + c), 8 gathers ---
    unsigned my8 = 0;
    #pragma unroll
    for (int c = 0; c < 2; c++) {
        const int cb = 2 * part + c;
        int e = 0;
        #pragma unroll
        for (int t = 0; t < 4; t++) {
            const int idx = cb * 4 + t;
            float v = 0.0f;
            if ((vm >> s_kpos[idx]) & 1u) v = __ldg(xb + s_off[idx]);
            const float thr = s_sval[cb * 32 + t * 8 + e];
            e = 2 * e + (v >= thr ? 1 : 0);
        }
        my8 |= (unsigned)e << (4 * c);
    }

    // Assemble all 16 nibbles: lanes l^1, l^2, l^4 are the other parts of
    // this pixel (pixel occupies bits 3..4 of the lane id).
    unsigned long long codes = (unsigned long long)my8 << (8 * part);
    codes |= __shfl_xor_sync(0xffffffffu, codes, 1);
    codes |= __shfl_xor_sync(0xffffffffu, codes, 2);
    codes |= __shfl_xor_sync(0xffffffffu, codes, 4);

    // --- accumulate channel groups gA = part, gB = part+8 ---
    unsigned long long a0, a1, a2, a3;
    {
        const float4* bias4 = (const float4*)s_bias;
        float4 bA = bias4[part];
        float4 bB = bias4[part + 8];
        PACK_F32X2(a0, bA.x, bA.y);
        PACK_F32X2(a1, bA.z, bA.w);
        PACK_F32X2(a2, bB.x, bB.y);
        PACK_F32X2(a3, bB.z, bB.w);
    }

    #pragma unroll
    for (int cb = 0; cb < NCB; cb++) {
        const int e = (int)((codes >> (4 * cb)) & 15ull);
        const float4* row = s_lut + (cb * 16 + e) * 16;
        float4 vA = row[part];
        float4 vB = row[part + 8];
        unsigned long long t0, t1, t2, t3;
        PACK_F32X2(t0, vA.x, vA.y);
        PACK_F32X2(t1, vA.z, vA.w);
        PACK_F32X2(t2, vB.x, vB.y);
        PACK_F32X2(t3, vB.z, vB.w);
        ADD_F32X2(a0, a0, t0);
        ADD_F32X2(a1, a1, t1);
        ADD_F32X2(a2, a2, t2);
        ADD_F32X2(a3, a3, t3);
    }

    // --- transpose through smem (reuse dead LUT region) for coalesced stores ---
    __syncthreads();
    float4* s_buf = (float4*)smem_raw;         // [g:16][pix:64], pix XOR-swizzled
    const int pix = tid >> 3;                  // local pixel 0..63
    {
        float f0, f1, f2, f3;
        UNPACK_F32X2(f0, f1, a0);
        UNPACK_F32X2(f2, f3, a1);
        s_buf[part * 64 + (pix ^ part)] = make_float4(f0, f1, f2, f3);
        UNPACK_F32X2(f0, f1, a2);
        UNPACK_F32X2(f2, f3, a3);
        s_buf[(part + 8) * 64 + (pix ^ part)] = make_float4(f0, f1, f2, f3);
    }
    __syncthreads();

    // --- coalesced stores: thread (g0 = tid>>6, q = tid&63) handles groups
    //     g0 and g0+8 for local pixel q. 3136/64 = 49 -> blocks never cross b.
    const int g0 = tid >> 6;
    const int q  = tid & 63;
    const int pg = blockIdx.x * 64 + q;        // global pixel
    const int bb = pg / HW;
    const int rr = pg - bb * HW;
    float* ob = out + (size_t)bb * 64 * HW + rr;

    float4 vA = s_buf[g0 * 64 + (q ^ g0)];
    float4 vB = s_buf[(g0 + 8) * 64 + (q ^ g0)];
    ob[(4 * g0 + 0) * HW] = vA.x;
    ob[(4 * g0 + 1) * HW] = vA.y;
    ob[(4 * g0 + 2) * HW] = vA.z;
    ob[(4 * g0 + 3) * HW] = vA.w;
    ob[(4 * (g0 + 8) + 0) * HW] = vB.x;
    ob[(4 * (g0 + 8) + 1) * HW] = vB.y;
    ob[(4 * (g0 + 8) + 2) * HW] = vB.z;
    ob[(4 * (g0 + 8) + 3) * HW] = vB.w;
}

extern "C" void kernel_launch(void* const* d_in, const int* in_sizes, int n_in,
                              void* d_out, int out_size)
{
    const float* x    = (const float*)d_in[0];
    const int*   sidx = (const int*)  d_in[1];
    const float* sval = (const float*)d_in[2];
    const float* lut  = (const float*)d_in[3];
    const float* bias = (const float*)d_in[4];
    float* out = (float*)d_out;

    cudaFuncSetAttribute(maddness_conv2d_kernel,
                         cudaFuncAttributeMaxDynamicSharedMemorySize,
                         SMEM_BYTES);

    maddness_conv2d_kernel<<<NBLK, TPB, SMEM_BYTES>>>(x, sidx, sval, lut, bias, out);
}

// round 5
// speedup vs baseline: 1.2020x; 1.2020x over previous
#include <cuda_runtime.h>
#include <cuda_bf16.h>
#include <cstdint>

// MaddnessConv2d, round 5: R3 structure, 2 lanes/pixel, 24 warps/SM.
//
//   x:            (16, 64, 56, 56) f32
//   split_idxs:   (16, 4) i32
//   split_vals:   (16, 4, 8) f32
//   lookup_tables:(16, 16, 64) f32
//   bias:         (64,) f32
//   out:          (16, 64, 56, 56) f32
//
// Per pixel: 16 4-bit codes (4 threshold steps on 4 fixed gathered x scalars
// per codebook), then out[ch] = sum_cb LUT[cb][e_cb][ch] + bias[ch].
//
// 2 lanes share a pixel (part = lane&1). Lane accumulates the 8 channel
// groups {even|part}; visitation order rotated by pixel so that each 8-lane
// LDS phase (4 pixels x 2 parts) hits banks (2rr+2pix+part)&7 = all 8,
// regardless of the data-dependent code e. Register index rr is static;
// group meaning g(rr) = ((2rr + 2(pix&7)) & 15) | part, un-rotated through
// a stride-132 smem transpose reusing the dead LUT region.

#define NCB   16
#define KENC  16
#define HW    3136          // 56*56
#define WID   56
#define NPIX  50176         // 16*56*56
#define TPB   256
#define NBLK  392           // 392*256 == 2*50176 exactly; 128 pixels/block

// dynamic smem layout:
//   float4 s_lut[16*16*16]   65536 B  (identity; reused as [16][132] float4 buf)
//   float  s_bias[64]          256 B
//   float  s_sval[16*4*8]     2048 B
//   int    s_off[64]           256 B
//   int    s_kpos[64]          256 B
#define SMEM_BYTES (65536 + 256 + 2048 + 256 + 256)

#define ADD_F32X2(out, a, b) \
    asm("add.rn.f32x2 %0, %1, %2;" : "=l"(out) : "l"(a), "l"(b))
#define PACK_F32X2(out, lo, hi) \
    asm("mov.b64 %0, {%1, %2;}" : "=l"(out) : "f"(lo), "f"(hi))
#undef PACK_F32X2
#define PACK_F32X2(out, lo, hi) \
    asm("mov.b64 %0, {%1, %2};" : "=l"(out) : "f"(lo), "f"(hi))
#define UNPACK_F32X2(lo, hi, in) \
    asm("mov.b64 {%0, %1}, %2;" : "=f"(lo), "=f"(hi) : "l"(in))

__global__ __launch_bounds__(TPB, 3) void maddness_conv2d_kernel(
    const float* __restrict__ x,
    const int*   __restrict__ split_idxs,
    const float* __restrict__ split_vals,
    const float* __restrict__ lut,
    const float* __restrict__ bias,
    float*       __restrict__ out)
{
    extern __shared__ char smem_raw[];
    float4* s_lut  = (float4*)smem_raw;
    float*  s_bias = (float*)(smem_raw + 65536);
    float*  s_sval = (float*)(smem_raw + 65536 + 256);
    int*    s_off  = (int*)  (smem_raw + 65536 + 256 + 2048);
    int*    s_kpos = (int*)  (smem_raw + 65536 + 256 + 2048 + 256);

    const int tid = threadIdx.x;

    // --- cooperative smem fill (LUT identity layout) ---
    const float4* lut4 = (const float4*)lut;
    #pragma unroll
    for (int i = tid; i < NCB * KENC * 16; i += TPB) s_lut[i] = lut4[i];
    if (tid < 64) {
        int cb = tid >> 2;                     // tid = cb*4 + t
        int si = split_idxs[tid];
        int f  = cb * 36 + si;
        int ch = f / 9;
        int r  = f - ch * 9;                   // kernel position 0..8
        int dy = r / 3 - 1;
        int dx = r - (r / 3) * 3 - 1;
        s_off[tid]  = ch * HW + dy * WID + dx;
        s_kpos[tid] = r;
        s_bias[tid] = bias[tid];
    }
    #pragma unroll
    for (int i = tid; i < NCB * 32; i += TPB) s_sval[i] = split_vals[i];
    __syncthreads();

    // --- indices: 2 lanes per pixel ---
    const int gt   = blockIdx.x * TPB + tid;   // exact grid
    const int p    = gt >> 1;                  // pixel
    const int part = gt & 1;
    const int b    = p / HW;
    const int rem  = p - b * HW;
    const int y    = rem / WID;
    const int xw   = rem - y * WID;
    const float* xb = x + (size_t)b * 64 * HW + rem;

    // 3x3 validity bitmask (pad=1)
    unsigned vm = 0;
    #pragma unroll
    for (int ki = 0; ki < 3; ki++)
        #pragma unroll
        for (int kj = 0; kj < 3; kj++) {
            bool ok = ((unsigned)(y + ki - 1) < 56u) & ((unsigned)(xw + kj - 1) < 56u);
            vm |= (ok ? 1u : 0u) << (ki * 3 + kj);
        }

    // --- encode my 8 codebooks (cb = 8*part + c) ---
    unsigned mine = 0;
    #pragma unroll
    for (int c = 0; c < 8; c++) {
        const int cb = 8 * part + c;
        int e = 0;
        #pragma unroll
        for (int t = 0; t < 4; t++) {
            const int idx = cb * 4 + t;
            float v = 0.0f;
            if ((vm >> s_kpos[idx]) & 1u) v = __ldg(xb + s_off[idx]);
            const float thr = s_sval[cb * 32 + t * 8 + e];
            e = 2 * e + (v >= thr ? 1 : 0);
        }
        mine |= (unsigned)e << (4 * c);
    }

    // Merge: lane^1 is the other part of this pixel. One shuffle only.
    unsigned long long codes = (unsigned long long)mine << (32 * part);
    codes |= __shfl_xor_sync(0xffffffffu, codes, 1);

    // --- accumulate; acc[rr] holds group g(rr) = ((2rr + rot2)&15) | part ---
    const int rot2 = (p & 7) * 2;
    // precompute even slot offsets (in float4 granules)
    int soff[8];
    #pragma unroll
    for (int rr = 0; rr < 8; rr++) soff[rr] = ((2 * rr + rot2) & 15);

    unsigned long long accA[8], accB[8];
    #pragma unroll
    for (int rr = 0; rr < 8; rr++) { accA[rr] = 0ull; accB[rr] = 0ull; }

    #pragma unroll
    for (int cb = 0; cb < NCB; cb++) {
        const int e = (int)((codes >> (4 * cb)) & 15ull);
        const float4* row = s_lut + (cb * 16 + e) * 16 + part;
        #pragma unroll
        for (int rr = 0; rr < 8; rr++) {
            float4 v = row[soff[rr]];
            unsigned long long lo, hi;
            PACK_F32X2(lo, v.x, v.y);
            PACK_F32X2(hi, v.z, v.w);
            ADD_F32X2(accA[rr], accA[rr], lo);
            ADD_F32X2(accB[rr], accB[rr], hi);
        }
    }

    // --- un-rotate via smem transpose (reuse dead LUT region) ---
    __syncthreads();
    float4* s_buf = (float4*)smem_raw;         // [g:16][px:132] (stride pad)
    const int pxl = tid >> 1;                  // local pixel 0..127
    #pragma unroll
    for (int rr = 0; rr < 8; rr++) {
        const int g = soff[rr] | part;
        float f0, f1, f2, f3;
        UNPACK_F32X2(f0, f1, accA[rr]);
        UNPACK_F32X2(f2, f3, accB[rr]);
        s_buf[g * 132 + pxl] = make_float4(f0, f1, f2, f3);
    }
    __syncthreads();

    // --- coalesced stores with bias: thread (q2 = tid>>7, pq = tid&127)
    //     stores groups q2*8 .. q2*8+7 for local pixel pq.
    const int q2 = tid >> 7;
    const int pq = tid & 127;
    const int pg = blockIdx.x * 128 + pq;      // global pixel
    const int bb = pg / HW;
    const int rr2 = pg - bb * HW;
    float* ob = out + (size_t)bb * 64 * HW + rr2;
    const float4* bias4 = (const float4*)s_bias;

    #pragma unroll
    for (int j = 0; j < 8; j++) {
        const int g = q2 * 8 + j;
        float4 v  = s_buf[g * 132 + pq];
        float4 bv = bias4[g];
        ob[(4 * g + 0) * HW] = v.x + bv.x;
        ob[(4 * g + 1) * HW] = v.y + bv.y;
        ob[(4 * g + 2) * HW] = v.z + bv.z;
        ob[(4 * g + 3) * HW] = v.w + bv.w;
    }
}

extern "C" void kernel_launch(void* const* d_in, const int* in_sizes, int n_in,
                              void* d_out, int out_size)
{
    const float* x    = (const float*)d_in[0];
    const int*   sidx = (const int*)  d_in[1];
    const float* sval = (const float*)d_in[2];
    const float* lut  = (const float*)d_in[3];
    const float* bias = (const float*)d_in[4];
    float* out = (float*)d_out;

    cudaFuncSetAttribute(maddness_conv2d_kernel,
                         cudaFuncAttributeMaxDynamicSharedMemorySize,
                         SMEM_BYTES);

    maddness_conv2d_kernel<<<NBLK, TPB, SMEM_BYTES>>>(x, sidx, sval, lut, bias, out);
}

// round 7
// speedup vs baseline: 1.5965x; 1.3282x over previous
#include <cuda_runtime.h>
#include <cuda_fp16.h>
#include <cstdint>

// MaddnessConv2d, round 7: fp16 LUT (halved LDS bytes) + HADD2 accumulation,
// R5 structure (2 lanes/pixel, rotation-conflict-free, 1 shuffle, 24 warps/SM).
// NOTE: tcgen05 is compile-blocked (harness ptxas targets sm_103, not sm_103a).
//
//   x:            (16, 64, 56, 56) f32
//   split_idxs:   (16, 4) i32
//   split_vals:   (16, 4, 8) f32
//   lookup_tables:(16, 16, 64) f32
//   bias:         (64,) f32
//   out:          (16, 64, 56, 56) f32
//
// out[p][ch] = sum_cb LUT[cb][e_cb(p)][ch] + bias[ch]; LUT held in smem as
// fp16 (row (cb,e) = 128B = 8 slots of 8 channels). Lane part in {0,1} of a
// pixel accumulates 4 slots s(rr) = ((2rr + 2(p&3))&7)|part in fp16; each
// 8-lane LDS phase (4 pixels x 2 parts) hits 8 distinct banks independent of
// the data-dependent code e. fp32 finalize (+bias) at the coalesced store.

#define NCB   16
#define HW    3136          // 56*56
#define WID   56
#define TPB   256
#define NBLK  392           // 392*256 == 2*50176 exactly; 128 pixels/block

// smem layout:
//   half  s_lut[16*16*64]    32768 B  (reused as [8][132] float4 transpose buf)
//   float s_bias[64]           256 B
//   float s_sval[16*4*8]      2048 B
//   int   s_off[64]            256 B
//   int   s_kpos[64]           256 B
#define SM_LUT   0
#define SM_BIAS  32768
#define SM_SVAL  33024
#define SM_OFF   35072
#define SM_KPOS  35328
#define SMEM_BYTES 35584

__global__ __launch_bounds__(TPB, 3) void maddness_conv2d_kernel(
    const float* __restrict__ x,
    const int*   __restrict__ split_idxs,
    const float* __restrict__ split_vals,
    const float* __restrict__ lut,
    const float* __restrict__ bias,
    float*       __restrict__ out)
{
    extern __shared__ char smem_raw[];
    char*  s_lutb = smem_raw + SM_LUT;
    float* s_bias = (float*)(smem_raw + SM_BIAS);
    float* s_sval = (float*)(smem_raw + SM_SVAL);
    int*   s_off  = (int*)  (smem_raw + SM_OFF);
    int*   s_kpos = (int*)  (smem_raw + SM_KPOS);

    const int tid = threadIdx.x;

    // --- cooperative smem fill: LUT fp32 -> fp16, row-major 128B rows ---
    // row r = cb*16+e holds ch 0..63 as half at byte r*128 + ch*2.
    {
        const float4* lut4 = (const float4*)lut;   // 4096 float4 (4 ch each)
        #pragma unroll
        for (int i = tid; i < 4096; i += TPB) {
            float4 lv = lut4[i];
            __half2 h0 = __floats2half2_rn(lv.x, lv.y);
            __half2 h1 = __floats2half2_rn(lv.z, lv.w);
            uint2 pk;
            pk.x = *(unsigned*)&h0;
            pk.y = *(unsigned*)&h1;
            // i = row*16 + ch4  (ch4 = group of 4 channels)
            *(uint2*)(s_lutb + (i >> 4) * 128 + (i & 15) * 8) = pk;
        }
    }
    if (tid < 64) {
        int cb = tid >> 2;                     // tid = cb*4 + t
        int si = split_idxs[tid];
        int f  = cb * 36 + si;
        int ch = f / 9;
        int r  = f - ch * 9;                   // kernel position 0..8
        int dy = r / 3 - 1;
        int dx = r - (r / 3) * 3 - 1;
        s_off[tid]  = ch * HW + dy * WID + dx;
        s_kpos[tid] = r;
        s_bias[tid] = bias[tid];
    }
    #pragma unroll
    for (int i = tid; i < NCB * 32; i += TPB) s_sval[i] = split_vals[i];
    __syncthreads();

    // --- indices: 2 lanes per pixel ---
    const int gt   = blockIdx.x * TPB + tid;   // exact grid
    const int p    = gt >> 1;                  // pixel
    const int part = gt & 1;
    const int b    = p / HW;
    const int rem  = p - b * HW;
    const int y    = rem / WID;
    const int xw   = rem - y * WID;
    const float* xb = x + (size_t)b * 64 * HW + rem;

    // 3x3 validity bitmask (pad=1)
    unsigned vm = 0;
    #pragma unroll
    for (int ki = 0; ki < 3; ki++)
        #pragma unroll
        for (int kj = 0; kj < 3; kj++) {
            bool ok = ((unsigned)(y + ki - 1) < 56u) & ((unsigned)(xw + kj - 1) < 56u);
            vm |= (ok ? 1u : 0u) << (ki * 3 + kj);
        }

    // --- encode my 8 codebooks (cb = 8*part + c) ---
    unsigned mine = 0;
    #pragma unroll
    for (int c = 0; c < 8; c++) {
        const int cb = 8 * part + c;
        int e = 0;
        #pragma unroll
        for (int t = 0; t < 4; t++) {
            const int idx = cb * 4 + t;
            float v = 0.0f;
            if ((vm >> s_kpos[idx]) & 1u) v = __ldg(xb + s_off[idx]);
            const float thr = s_sval[cb * 32 + t * 8 + e];
            e = 2 * e + (v >= thr ? 1 : 0);
        }
        mine |= (unsigned)e << (4 * c);
    }

    // Merge: lane^1 is the other part of this pixel. One shuffle only.
    unsigned long long codes = (unsigned long long)mine << (32 * part);
    codes |= __shfl_xor_sync(0xffffffffu, codes, 1);

    // --- accumulate in fp16: acc[rr] = slot s(rr) = ((2rr + rot2)&7)|part ---
    const int rot2 = (p & 3) * 2;
    int soff[4];
    #pragma unroll
    for (int rr = 0; rr < 4; rr++) soff[rr] = (((2 * rr + rot2) & 7) | part) * 16;

    __half2 acc[4][4];
    #pragma unroll
    for (int rr = 0; rr < 4; rr++)
        #pragma unroll
        for (int k = 0; k < 4; k++) acc[rr][k] = __half2half2(__ushort_as_half(0));

    #pragma unroll
    for (int cb = 0; cb < NCB; cb++) {
        const int e = (int)((codes >> (4 * cb)) & 15ull);
        const char* row = s_lutb + (cb * 16 + e) * 128;
        #pragma unroll
        for (int rr = 0; rr < 4; rr++) {
            uint4 v = *(const uint4*)(row + soff[rr]);
            acc[rr][0] = __hadd2(acc[rr][0], *(__half2*)&v.x);
            acc[rr][1] = __hadd2(acc[rr][1], *(__half2*)&v.y);
            acc[rr][2] = __hadd2(acc[rr][2], *(__half2*)&v.z);
            acc[rr][3] = __hadd2(acc[rr][3], *(__half2*)&v.w);
        }
    }

    // --- un-rotate via smem transpose (reuse dead LUT region) ---
    __syncthreads();
    float4* s_buf = (float4*)smem_raw;         // [g:8][px:132] float4 of 4 half2
    const int pxl = tid >> 1;                  // local pixel 0..127
    #pragma unroll
    for (int rr = 0; rr < 4; rr++) {
        const int g = soff[rr] >> 4;           // channel-8 group 0..7
        float4 v;
        v.x = *(float*)&acc[rr][0];            // bit reinterpret (2 halves)
        v.y = *(float*)&acc[rr][1];
        v.z = *(float*)&acc[rr][2];
        v.w = *(float*)&acc[rr][3];
        s_buf[g * 132 + pxl] = v;
    }
    __syncthreads();

    // --- coalesced stores with fp32 finalize + bias ---
    // thread (q2 = tid>>7, pq = tid&127) stores groups q2*4 .. q2*4+3.
    const int q2 = tid >> 7;
    const int pq = tid & 127;
    const int pg = blockIdx.x * 128 + pq;      // global pixel
    const int bb = pg / HW;
    const int rr2 = pg - bb * HW;
    float* ob = out + (size_t)bb * 64 * HW + rr2;

    #pragma unroll
    for (int j = 0; j < 4; j++) {
        const int g = q2 * 4 + j;
        float4 v = s_buf[g * 132 + pq];
        float2 f0 = __half22float2(*(__half2*)&v.x);
        float2 f1 = __half22float2(*(__half2*)&v.y);
        float2 f2 = __half22float2(*(__half2*)&v.z);
        float2 f3 = __half22float2(*(__half2*)&v.w);
        const int ch = 8 * g;
        ob[(ch + 0) * HW] = f0.x + s_bias[ch + 0];
        ob[(ch + 1) * HW] = f0.y + s_bias[ch + 1];
        ob[(ch + 2) * HW] = f1.x + s_bias[ch + 2];
        ob[(ch + 3) * HW] = f1.y + s_bias[ch + 3];
        ob[(ch + 4) * HW] = f2.x + s_bias[ch + 4];
        ob[(ch + 5) * HW] = f2.y + s_bias[ch + 5];
        ob[(ch + 6) * HW] = f3.x + s_bias[ch + 6];
        ob[(ch + 7) * HW] = f3.y + s_bias[ch + 7];
    }
}

extern "C" void kernel_launch(void* const* d_in, const int* in_sizes, int n_in,
                              void* d_out, int out_size)
{
    const float* x    = (const float*)d_in[0];
    const int*   sidx = (const int*)  d_in[1];
    const float* sval = (const float*)d_in[2];
    const float* lut  = (const float*)d_in[3];
    const float* bias = (const float*)d_in[4];
    float* out = (float*)d_out;

    cudaFuncSetAttribute(maddness_conv2d_kernel,
                         cudaFuncAttributeMaxDynamicSharedMemorySize,
                         SMEM_BYTES);

    maddness_conv2d_kernel<<<NBLK, TPB, SMEM_BYTES>>>(x, sidx, sval, lut, bias, out);
}